// round 6
// baseline (speedup 1.0000x reference)
#include <cuda_runtime.h>
#include <cuda_bf16.h>

// DurationCalculator:
//   weights_argmax[b,y] = duration[b,y] + (y < output_length[b] ? 0 : -10000)
//   durations[b,x]      = count over y of (weights_argmax[b,y] == x), 0 <= x < X
// Output (float32): [ weights_argmax (B*Y) | durations (B*X) ]
//
// Row split across S CTAs (grid = S x B) for occupancy; per-CTA smem histogram
// merged into pre-zeroed h_out via float atomicAdd (exact for integer counts).

#ifndef MASK_PENALTY
#define MASK_PENALTY (-10000)
#endif

__global__ void __launch_bounds__(512)
duration_calc_kernel(const int* __restrict__ duration,
                     const int* __restrict__ output_length,
                     float* __restrict__ w_out,
                     float* __restrict__ h_out,
                     int Y, int X, int chunk4)   // chunk4 = int4s per split CTA
{
    extern __shared__ int hist[];  // X bins
    const int b   = blockIdx.y;
    const int s   = blockIdx.x;
    const int tid = threadIdx.x;
    const int nt  = blockDim.x;    // 512

    for (int i = tid; i < X; i += nt) hist[i] = 0;
    __syncthreads();

    const int L  = output_length[b];
    const int n4 = Y >> 2;
    const int lo = s * chunk4;
    int hi = lo + chunk4; if (hi > n4) hi = n4;

    const int4* __restrict__ dur4 = reinterpret_cast<const int4*>(duration + (size_t)b * Y);
    float4* __restrict__ w4       = reinterpret_cast<float4*>(w_out + (size_t)b * Y);

    for (int i = lo + tid; i < hi; i += nt) {
        const int y = i << 2;
        int4 d = dur4[i];
        int wx = d.x + ((y + 0) < L ? 0 : MASK_PENALTY);
        int wy = d.y + ((y + 1) < L ? 0 : MASK_PENALTY);
        int wz = d.z + ((y + 2) < L ? 0 : MASK_PENALTY);
        int ww = d.w + ((y + 3) < L ? 0 : MASK_PENALTY);
        float4 w;
        w.x = (float)wx; w.y = (float)wy; w.z = (float)wz; w.w = (float)ww;
        w4[i] = w;
        if ((unsigned)wx < (unsigned)X) atomicAdd(&hist[wx], 1);
        if ((unsigned)wy < (unsigned)X) atomicAdd(&hist[wy], 1);
        if ((unsigned)wz < (unsigned)X) atomicAdd(&hist[wz], 1);
        if ((unsigned)ww < (unsigned)X) atomicAdd(&hist[ww], 1);
    }

    // Scalar tail for Y not a multiple of 4 (no-op for Y=4096); last split only.
    if (s == gridDim.x - 1) {
        for (int y = (n4 << 2) + tid; y < Y; y += nt) {
            int w = duration[(size_t)b * Y + y] + (y < L ? 0 : MASK_PENALTY);
            w_out[(size_t)b * Y + y] = (float)w;
            if ((unsigned)w < (unsigned)X) atomicAdd(&hist[w], 1);
        }
    }

    __syncthreads();

    // Merge partial histogram into global (pre-zeroed) float output.
    float* __restrict__ hrow = h_out + (size_t)b * X;
    for (int i = tid; i < X; i += nt) {
        int c = hist[i];
        if (c) atomicAdd(&hrow[i], (float)c);   // exact: integer-valued fp32
    }
}

extern "C" void kernel_launch(void* const* d_in, const int* in_sizes, int n_in,
                              void* d_out, int out_size)
{
    const int* duration      = (const int*)d_in[0];
    const int* output_length = (const int*)d_in[1];

    const int B = in_sizes[1];          // 256
    const int Y = in_sizes[0] / B;      // 4096
    const int X = out_size / B - Y;     // 1024

    float* w_out = (float*)d_out;                   // weights_argmax: B*Y
    float* h_out = (float*)d_out + (size_t)B * Y;   // durations:      B*X

    // Zero the histogram region (0x00000000 == 0.0f), same stream => ordered.
    cudaMemsetAsync(h_out, 0, (size_t)B * X * sizeof(float), 0);

    const int S = 2;                    // splits per row
    const int n4 = Y >> 2;
    const int chunk4 = (n4 + S - 1) / S;

    dim3 grid(S, B);
    const int threads = 512;
    const size_t smem = (size_t)X * sizeof(int);
    duration_calc_kernel<<<grid, threads, smem>>>(duration, output_length,
                                                  w_out, h_out, Y, X, chunk4);
}